// round 16
// baseline (speedup 1.0000x reference)
#include <cuda_runtime.h>
#include <cuda_fp16.h>
#include <cstdint>

#define N_NODES 40000
#define N_EDGES 800000
#define IN_DIM  128
#define COM_DIM 128
#define N_ETYPE 5
#define N_HEADS 4
#define NCH     20
#define ELSTRIDE 32
#define NEG_SLOPE 0.2f
#define LOG2E 1.4426950408889634f
#define TILE_M 128
#define NTILES 313            // ceil(40000/128)
#define NPAD   (NTILES * TILE_M)   // 40064
#define APITCH 36             // A chunk pitch (words)
#define BPITCH 136            // B chunk pitch (words)
#define CPITCH 132
#define SCAN_BLK 40
#define ELP 21                // staged el row pitch (words)

// smem float offsets (dynamic) for mma
#define A0OFF 0               // 128*36 = 4608
#define A1OFF 4608
#define B0OFF 9216            // 32*136 = 4352
#define B1OFF 13568
#define SH_WORDS 17920        // 71680 B; sC[128][132]=16896 overlays at 0

// ---------------- device scratch ----------------
__device__ __half   g_messh[(size_t)N_ETYPE * N_NODES * COM_DIM];  // 51.2 MB
__device__ float    g_el[(size_t)N_NODES * ELSTRIDE];
__device__ float    g_er[(size_t)N_NODES * ELSTRIDE];
__device__ float    g_enum[(size_t)N_EDGES * 4];                   // deg>64 fallback
__device__ uint32_t g_featr[(size_t)NPAD * IN_DIM];                // tf32-rounded feat
__device__ uint32_t g_wr[(size_t)N_ETYPE * IN_DIM * COM_DIM];      // tf32-rounded W
__device__ int      g_deg[N_NODES];
__device__ int      g_rowptr[N_NODES + 1];
__device__ int      g_eidx[N_EDGES];
__device__ int      g_bsum[SCAN_BLK];
__device__ int      g_boff[SCAN_BLK];

__device__ __forceinline__ void mma_tf32(float* c, uint32_t a0, uint32_t a1,
                                         uint32_t a2, uint32_t a3,
                                         uint32_t b0, uint32_t b1) {
    asm volatile(
        "mma.sync.aligned.m16n8k8.row.col.f32.tf32.tf32.f32 "
        "{%0,%1,%2,%3}, {%4,%5,%6,%7}, {%8,%9}, {%0,%1,%2,%3};"
        : "+f"(c[0]), "+f"(c[1]), "+f"(c[2]), "+f"(c[3])
        : "r"(a0), "r"(a1), "r"(a2), "r"(a3), "r"(b0), "r"(b1));
}
__device__ __forceinline__ uint32_t rndf(float x) {
    uint32_t r;
    asm("cvt.rna.tf32.f32 %0, %1;" : "=r"(r) : "f"(x));
    return r;
}
__device__ __forceinline__ float ex2(float x) {
    float r;
    asm("ex2.approx.f32 %0, %1;" : "=f"(r) : "f"(x));
    return r;
}
__device__ __forceinline__ void cp16(uint32_t saddr, const void* g) {
    asm volatile("cp.async.cg.shared.global [%0], [%1], 16;" :: "r"(saddr), "l"(g));
}
__device__ __forceinline__ void cp4(uint32_t saddr, const void* g) {
    asm volatile("cp.async.ca.shared.global [%0], [%1], 4;" :: "r"(saddr), "l"(g));
}
#define CP_COMMIT() asm volatile("cp.async.commit_group;" ::: "memory")
#define CP_WAIT(N)  asm volatile("cp.async.wait_group %0;" :: "n"(N) : "memory")

// ---------------- Phase 0: pre-round feat & W to tf32 bits ----------------
__global__ __launch_bounds__(256) void preround_kernel(
    const float* __restrict__ feat, const float* __restrict__ W)
{
    int i = blockIdx.x * blockDim.x + threadIdx.x;
    if (i < (NPAD * IN_DIM) / 4) {
        float4 v = (i < (N_NODES * IN_DIM) / 4) ? ((const float4*)feat)[i]
                                                : make_float4(0.f, 0.f, 0.f, 0.f);
        uint4 o;
        o.x = rndf(v.x); o.y = rndf(v.y); o.z = rndf(v.z); o.w = rndf(v.w);
        ((uint4*)g_featr)[i] = o;
    }
    if (i < (N_ETYPE * IN_DIM * COM_DIM) / 4) {
        float4 v = ((const float4*)W)[i];
        uint4 o;
        o.x = rndf(v.x); o.y = rndf(v.y); o.z = rndf(v.z); o.w = rndf(v.w);
        ((uint4*)g_wr)[i] = o;
    }
}

// ---------------- Phase 1: mess = mask*(feat@W_t)+com, fused el/er ----------------
// 128Mx128N block tile, 8 warps (32Mx64N each), 2 CTAs/SM.
__global__ __launch_bounds__(256, 2)
void mma_kernel(const float* __restrict__ com, const float* __restrict__ mask,
                const float* __restrict__ attn_l, const float* __restrict__ attn_r)
{
    __shared__ float sAttn[8 * CPITCH];   // pre-scaled by log2(e)
    __shared__ float sMask[TILE_M];
    extern __shared__ float sh[];

    const int tid = threadIdx.x;
    const int wid = tid >> 5, lane = tid & 31;
    const int g = lane >> 2, tig = lane & 3;
    const int t = blockIdx.y;
    const int n0 = blockIdx.x * TILE_M;

    uint32_t shu;
    asm("{ .reg .u64 x; cvta.to.shared.u64 x, %1; cvt.u32.u64 %0, x; }" : "=r"(shu) : "l"(sh));

    for (int i = tid; i < 1024; i += 256) {
        int h = i >> 7, c = i & 127;
        float a = (h < 4) ? attn_l[(t * 4 + h) * 128 + c]
                          : attn_r[(t * 4 + (h - 4)) * 128 + c];
        sAttn[h * CPITCH + c] = a * LOG2E;
    }
    if (tid < TILE_M) {
        int gr = n0 + tid;
        sMask[tid] = (gr < N_NODES) ? mask[gr * N_ETYPE + t] : 0.f;
    }

    const uint32_t* Wt = g_wr + (size_t)t * IN_DIM * COM_DIM;

    auto load_chunk = [&](int c) {
        uint32_t abuf = shu + (uint32_t)((c & 1) ? A1OFF : A0OFF) * 4u;
        uint32_t bbuf = shu + (uint32_t)((c & 1) ? B1OFF : B0OFF) * 4u;
        #pragma unroll
        for (int jj = 0; jj < 4; ++jj) {                 // A: 128 x 32 words
            int j = tid + jj * 256;
            int row = j >> 3, seg = j & 7;
            cp16(abuf + (uint32_t)(row * APITCH + seg * 4) * 4u,
                 g_featr + (size_t)(n0 + row) * 128 + c * 32 + seg * 4);
        }
        #pragma unroll
        for (int jj = 0; jj < 4; ++jj) {                 // B: 32 x 128 words
            int j = tid + jj * 256;
            int kr = j >> 5, seg = j & 31;
            cp16(bbuf + (uint32_t)(kr * BPITCH + seg * 4) * 4u,
                 Wt + (size_t)(c * 32 + kr) * 128 + seg * 4);
        }
        CP_COMMIT();
    };

    const int mrow = (wid & 3) * 32;
    const int ncol = (wid >> 2) * 64;
    float acc[2][8][4];
    #pragma unroll
    for (int mb = 0; mb < 2; ++mb)
        #pragma unroll
        for (int nb = 0; nb < 8; ++nb)
            #pragma unroll
            for (int q = 0; q < 4; ++q) acc[mb][nb][q] = 0.f;

    load_chunk(0);
    for (int c = 0; c < 4; ++c) {
        if (c < 3) { load_chunk(c + 1); CP_WAIT(1); } else { CP_WAIT(0); }
        __syncthreads();

        const uint32_t* uA = (const uint32_t*)(sh + ((c & 1) ? A1OFF : A0OFF));
        const uint32_t* uB = (const uint32_t*)(sh + ((c & 1) ? B1OFF : B0OFF));
        #pragma unroll
        for (int ko = 0; ko < 32; ko += 8) {
            uint32_t a[2][4];
            #pragma unroll
            for (int mb = 0; mb < 2; ++mb) {
                int r = mrow + mb * 16;
                a[mb][0] = uA[(r + g) * APITCH + ko + tig];
                a[mb][1] = uA[(r + g + 8) * APITCH + ko + tig];
                a[mb][2] = uA[(r + g) * APITCH + ko + tig + 4];
                a[mb][3] = uA[(r + g + 8) * APITCH + ko + tig + 4];
            }
            #pragma unroll
            for (int nb = 0; nb < 8; ++nb) {
                int n = ncol + nb * 8 + g;
                uint32_t b0 = uB[(ko + tig) * BPITCH + n];
                uint32_t b1 = uB[(ko + tig + 4) * BPITCH + n];
                mma_tf32(acc[0][nb], a[0][0], a[0][1], a[0][2], a[0][3], b0, b1);
                mma_tf32(acc[1][nb], a[1][0], a[1][1], a[1][2], a[1][3], b0, b1);
            }
        }
        __syncthreads();
    }

    // ---- stage raw C into sC ----
    float* sC = sh;
    #pragma unroll
    for (int mb = 0; mb < 2; ++mb) {
        #pragma unroll
        for (int nb = 0; nb < 8; ++nb) {
            int r = mrow + mb * 16 + g;
            int cc = ncol + nb * 8 + 2 * tig;
            sC[r * CPITCH + cc]            = acc[mb][nb][0];
            sC[r * CPITCH + cc + 1]        = acc[mb][nb][1];
            sC[(r + 8) * CPITCH + cc]      = acc[mb][nb][2];
            sC[(r + 8) * CPITCH + cc + 1]  = acc[mb][nb][3];
        }
    }
    __syncthreads();

    // ---- mess pass: m = mk*C + com; fp16 -> gmem, fp32 -> sC ----
    for (int rr = 0; rr < 16; ++rr) {
        int r = wid * 16 + rr;
        int n = n0 + r;
        if (n >= N_NODES) break;
        float mk = sMask[r];
        float4 cv = *(const float4*)&sC[r * CPITCH + lane * 4];
        float4 cm = ((const float4*)com)[(size_t)n * 32 + lane];
        float4 m;
        m.x = fmaf(mk, cv.x, cm.x);
        m.y = fmaf(mk, cv.y, cm.y);
        m.z = fmaf(mk, cv.z, cm.z);
        m.w = fmaf(mk, cv.w, cm.w);
        __half2 h0 = __floats2half2_rn(m.x, m.y);
        __half2 h1 = __floats2half2_rn(m.z, m.w);
        uint2 pk;
        pk.x = *(uint32_t*)&h0;
        pk.y = *(uint32_t*)&h1;
        ((uint2*)(g_messh + ((size_t)t * N_NODES + n) * COM_DIM))[lane] = pk;
        *(float4*)&sC[r * CPITCH + lane * 4] = m;
    }
    __syncthreads();

    // ---- el/er dots (log2-scaled): lane = (row_sub, head) ----
    {
        const int r_sub = lane >> 3, v = lane & 7;
        #pragma unroll
        for (int it = 0; it < 4; ++it) {
            int r = wid * 16 + it * 4 + r_sub;
            int n = n0 + r;
            const float4* mrow4 = (const float4*)&sC[r * CPITCH];
            const float4* arow4 = (const float4*)&sAttn[v * CPITCH];
            float dot = 0.f;
            #pragma unroll
            for (int k4 = 0; k4 < 32; ++k4) {
                float4 mv = mrow4[k4];
                float4 av = arow4[k4];
                dot = fmaf(mv.x, av.x, dot);
                dot = fmaf(mv.y, av.y, dot);
                dot = fmaf(mv.z, av.z, dot);
                dot = fmaf(mv.w, av.w, dot);
            }
            if (n < N_NODES) {
                if (v < 4) g_el[(size_t)n * ELSTRIDE + v * N_ETYPE + t] = dot;
                else       g_er[(size_t)n * ELSTRIDE + (v - 4) * N_ETYPE + t] = dot;
            }
        }
    }
}

// ---------------- CSR build ----------------
__global__ void zero_kernel() {
    int i = blockIdx.x * blockDim.x + threadIdx.x;
    if (i < N_NODES) g_deg[i] = 0;
}
__global__ void hist_kernel(const int* __restrict__ dst) {
    int m = blockIdx.x * blockDim.x + threadIdx.x;
    if (m < N_EDGES) atomicAdd(&g_deg[dst[m]], 1);
}
__global__ __launch_bounds__(1024) void scanA_kernel() {
    __shared__ int wsum[32];
    const int tid = threadIdx.x, lane = tid & 31, wid = tid >> 5;
    int idx = blockIdx.x * 1024 + tid;
    int v = (idx < N_NODES) ? g_deg[idx] : 0;
    int x = v;
    #pragma unroll
    for (int off = 1; off < 32; off <<= 1) {
        int y = __shfl_up_sync(0xffffffffu, x, off);
        if (lane >= off) x += y;
    }
    if (lane == 31) wsum[wid] = x;
    __syncthreads();
    if (wid == 0) {
        int s = wsum[lane];
        #pragma unroll
        for (int off = 1; off < 32; off <<= 1) {
            int y = __shfl_up_sync(0xffffffffu, s, off);
            if (lane >= off) s += y;
        }
        wsum[lane] = s;
        if (lane == 31) g_bsum[blockIdx.x] = s;
    }
    __syncthreads();
    int excl = (x - v) + (wid > 0 ? wsum[wid - 1] : 0);
    if (idx < N_NODES) g_rowptr[idx] = excl;
}
__global__ void scanB_kernel() {
    int lane = threadIdx.x;
    int v = (lane < SCAN_BLK) ? g_bsum[lane] : 0;
    int x = v;
    #pragma unroll
    for (int off = 1; off < 32; off <<= 1) {
        int y = __shfl_up_sync(0xffffffffu, x, off);
        if (lane >= off) x += y;
    }
    __shared__ int tot32;
    if (lane == 31) tot32 = x;
    __syncwarp();
    g_boff[lane] = x - v;
    if (lane == 0) {
        int run = tot32;
        for (int b = 32; b < SCAN_BLK; ++b) {
            g_boff[b] = run;
            run += g_bsum[b];
        }
        g_rowptr[N_NODES] = N_EDGES;
    }
}
__global__ void scanC_kernel() {
    int i = blockIdx.x * blockDim.x + threadIdx.x;
    if (i < N_NODES) {
        int r = g_rowptr[i] + g_boff[i >> 10];
        g_rowptr[i] = r;
        g_deg[i] = r;
    }
}
__global__ void scatter_kernel(const int* __restrict__ dst) {
    int m = blockIdx.x * blockDim.x + threadIdx.x;
    if (m < N_EDGES) {
        int pos = atomicAdd(&g_deg[dst[m]], 1);
        g_eidx[pos] = m;
    }
}

// ---------------- Phase 3: softmax + aggregate + ELU (warp per dst) ----------------
__global__ __launch_bounds__(256) void agg_kernel(
    const int* __restrict__ src, const int* __restrict__ etype,
    float* __restrict__ out)
{
    __shared__ float sEl[8 * 32 * ELP];   // per-warp staging: 32 edges x ELP
    int warp = (blockIdx.x * blockDim.x + threadIdx.x) >> 5;
    if (warp >= N_NODES) return;
    const int lane = threadIdx.x & 31;
    const int w = (threadIdx.x >> 5);
    const int d = warp;
    const int beg = g_rowptr[d], end = g_rowptr[d + 1];

    float* sElW = sEl + w * 32 * ELP;
    uint32_t sElU;
    asm("{ .reg .u64 x; cvta.to.shared.u64 x, %1; cvt.u32.u64 %0, x; }" : "=r"(sElU) : "l"(sElW));

    float er_l = g_er[(size_t)d * ELSTRIDE + lane];   // log2 domain

    // ---- pass 1 ----
    float den = 0.f;
    float4 enreg[2];
    enreg[0] = make_float4(0.f, 0.f, 0.f, 0.f);
    enreg[1] = make_float4(0.f, 0.f, 0.f, 0.f);
    int ci = 0;
    for (int base = beg; base < end; base += 32, ++ci) {
        int cnt = min(32, end - base);
        int s = 0, tt = 0;
        if (lane < cnt) {
            int m = g_eidx[base + lane];
            s = src[m];
            tt = etype[m];
        }
        // stage el rows: edge p's 20 channels -> sElW[p*ELP + ch]  (lane = channel)
        for (int p = 0; p < cnt; ++p) {
            int sp = __shfl_sync(0xffffffffu, s, p);
            if (lane < NCH)                                  // BOUNDS GUARD (R15 fix)
                cp4(sElU + (uint32_t)(p * ELP + lane) * 4u,
                    g_el + (size_t)sp * ELSTRIDE + lane);
        }
        CP_COMMIT();
        CP_WAIT(0);
        __syncwarp();

        // dense exp2: lane = edge, loop channels
        float4 en = make_float4(0.f, 0.f, 0.f, 0.f);
        #pragma unroll
        for (int ch = 0; ch < NCH; ++ch) {
            float erb = __shfl_sync(0xffffffffu, er_l, ch);
            float v = sElW[lane * ELP + ch] + erb;
            v = v >= 0.f ? v : NEG_SLOPE * v;
            float e = 0.f;
            if (lane < cnt) e = ex2(v);
            if (ch == tt)            en.x = e;
            else if (ch == tt + 5)   en.y = e;
            else if (ch == tt + 10)  en.z = e;
            else if (ch == tt + 15)  en.w = e;
            float sum = e;
            #pragma unroll
            for (int off = 16; off; off >>= 1)
                sum += __shfl_xor_sync(0xffffffffu, sum, off);
            if (lane == ch) den += sum;
        }
        if (ci < 2) enreg[ci] = en;
        else if (lane < cnt) ((float4*)g_enum)[base + lane] = en;
        __syncwarp();
    }
    float inv_den = (lane < NCH && den > 0.f) ? 1.f / den : 0.f;

    // ---- pass 2 ----
    float4 acc = make_float4(0.f, 0.f, 0.f, 0.f);
    ci = 0;
    for (int base = beg; base < end; base += 32, ++ci) {
        int cnt = min(32, end - base);
        int ri = 0, tt = 0;
        float4 en = make_float4(0.f, 0.f, 0.f, 0.f);
        if (lane < cnt) {
            int m = g_eidx[base + lane];
            int s = src[m];
            tt = etype[m];
            ri = tt * N_NODES + s;
            en = (ci < 2) ? enreg[ci] : ((const float4*)g_enum)[base + lane];
        }
        float id0 = __shfl_sync(0xffffffffu, inv_den, tt);
        float id1 = __shfl_sync(0xffffffffu, inv_den, tt + 5);
        float id2 = __shfl_sync(0xffffffffu, inv_den, tt + 10);
        float id3 = __shfl_sync(0xffffffffu, inv_den, tt + 15);
        float cp = en.x * id0 + en.y * id1 + en.z * id2 + en.w * id3;

        for (int p0 = 0; p0 < cnt; p0 += 4) {
            int k = min(4, cnt - p0);
            uint2 pk[4];
            float cc[4];
            #pragma unroll
            for (int j = 0; j < 4; ++j) {
                if (j < k) {
                    int rj = __shfl_sync(0xffffffffu, ri, p0 + j);
                    cc[j] = __shfl_sync(0xffffffffu, cp, p0 + j);
                    pk[j] = ((const uint2*)(g_messh + (size_t)rj * COM_DIM))[lane];
                } else {
                    cc[j] = 0.f;
                    pk[j] = make_uint2(0u, 0u);
                }
            }
            #pragma unroll
            for (int j = 0; j < 4; ++j) {
                __half2 h0 = *(__half2*)&pk[j].x;
                __half2 h1 = *(__half2*)&pk[j].y;
                float2 f0 = __half22float2(h0);
                float2 f1 = __half22float2(h1);
                acc.x = fmaf(cc[j], f0.x, acc.x);
                acc.y = fmaf(cc[j], f0.y, acc.y);
                acc.z = fmaf(cc[j], f1.x, acc.z);
                acc.w = fmaf(cc[j], f1.y, acc.w);
            }
        }
    }
    float4 o;
    o.x = acc.x > 0.f ? acc.x : expm1f(acc.x);
    o.y = acc.y > 0.f ? acc.y : expm1f(acc.y);
    o.z = acc.z > 0.f ? acc.z : expm1f(acc.z);
    o.w = acc.w > 0.f ? acc.w : expm1f(acc.w);
    ((float4*)out)[(size_t)d * 32 + lane] = o;
}

// ---------------- launch ----------------
extern "C" void kernel_launch(void* const* d_in, const int* in_sizes, int n_in,
                              void* d_out, int out_size)
{
    const float* feat   = (const float*)d_in[0];
    const float* com    = (const float*)d_in[1];
    const float* mask   = (const float*)d_in[2];
    const float* W      = (const float*)d_in[3];
    const float* attn_l = (const float*)d_in[4];
    const float* attn_r = (const float*)d_in[5];
    const int*   src    = (const int*)d_in[6];
    const int*   dst    = (const int*)d_in[7];
    const int*   etype  = (const int*)d_in[8];
    float* out = (float*)d_out;

    const int smem = SH_WORDS * (int)sizeof(float);   // 71680 B
    cudaFuncSetAttribute(mma_kernel, cudaFuncAttributeMaxDynamicSharedMemorySize, smem);

    const int pr_grid = ((NPAD * IN_DIM) / 4 + 255) / 256;

    // mma_kernel kept at launch index 3 (ncu capture slot)
    zero_kernel<<<(N_NODES + 255) / 256, 256>>>();
    hist_kernel<<<(N_EDGES + 255) / 256, 256>>>(dst);
    preround_kernel<<<pr_grid, 256>>>(feat, W);
    mma_kernel<<<dim3(NTILES, N_ETYPE), 256, smem>>>(com, mask, attn_l, attn_r);
    scanA_kernel<<<SCAN_BLK, 1024>>>();
    scanB_kernel<<<1, 32>>>();
    scanC_kernel<<<(N_NODES + 255) / 256, 256>>>();
    scatter_kernel<<<(N_EDGES + 255) / 256, 256>>>(dst);
    agg_kernel<<<(N_NODES * 32 + 255) / 256, 256>>>(src, etype, out);
}

// round 17
// speedup vs baseline: 1.5161x; 1.5161x over previous
#include <cuda_runtime.h>
#include <cuda_fp16.h>
#include <cstdint>

#define N_NODES 40000
#define N_EDGES 800000
#define IN_DIM  128
#define COM_DIM 128
#define N_ETYPE 5
#define N_HEADS 4
#define NCH     20
#define ELSTRIDE 32
#define NEG_SLOPE 0.2f
#define LOG2E 1.4426950408889634f
#define TILE_M 128
#define NTILES 313            // ceil(40000/128)
#define NPAD   (NTILES * TILE_M)   // 40064
#define APITCH 36             // A chunk pitch (words)
#define BPITCH 136            // B chunk pitch (words)
#define CPITCH 132
#define SCAN_BLK 40
#define ELP 21                // staged el row pitch (words)

// smem float offsets (dynamic) for mma
#define A0OFF 0               // 128*36 = 4608
#define A1OFF 4608
#define B0OFF 9216            // 32*136 = 4352
#define B1OFF 13568
#define SH_WORDS 17920        // 71680 B; sC[128][132]=16896 overlays at 0

// ---------------- device scratch ----------------
__device__ __half   g_messh[(size_t)N_ETYPE * N_NODES * COM_DIM];  // 51.2 MB
__device__ float    g_el[(size_t)N_NODES * ELSTRIDE];
__device__ float    g_er[(size_t)N_NODES * ELSTRIDE];
__device__ float    g_enum[(size_t)N_EDGES * 4];                   // deg>64 fallback
__device__ uint32_t g_featr[(size_t)NPAD * IN_DIM];                // tf32-rounded feat
__device__ uint32_t g_wr[(size_t)N_ETYPE * IN_DIM * COM_DIM];      // tf32-rounded W
__device__ int      g_deg[N_NODES];
__device__ int      g_rowptr[N_NODES + 1];
__device__ int      g_epack[N_EDGES];                              // src | etype<<16, CSR order
__device__ int      g_bsum[SCAN_BLK];
__device__ int      g_boff[SCAN_BLK];

__device__ __forceinline__ void mma_tf32(float* c, uint32_t a0, uint32_t a1,
                                         uint32_t a2, uint32_t a3,
                                         uint32_t b0, uint32_t b1) {
    asm volatile(
        "mma.sync.aligned.m16n8k8.row.col.f32.tf32.tf32.f32 "
        "{%0,%1,%2,%3}, {%4,%5,%6,%7}, {%8,%9}, {%0,%1,%2,%3};"
        : "+f"(c[0]), "+f"(c[1]), "+f"(c[2]), "+f"(c[3])
        : "r"(a0), "r"(a1), "r"(a2), "r"(a3), "r"(b0), "r"(b1));
}
__device__ __forceinline__ uint32_t rndf(float x) {
    uint32_t r;
    asm("cvt.rna.tf32.f32 %0, %1;" : "=r"(r) : "f"(x));
    return r;
}
__device__ __forceinline__ float ex2(float x) {
    float r;
    asm("ex2.approx.f32 %0, %1;" : "=f"(r) : "f"(x));
    return r;
}
__device__ __forceinline__ void cp16(uint32_t saddr, const void* g) {
    asm volatile("cp.async.cg.shared.global [%0], [%1], 16;" :: "r"(saddr), "l"(g));
}
__device__ __forceinline__ void cp4(uint32_t saddr, const void* g) {
    asm volatile("cp.async.ca.shared.global [%0], [%1], 4;" :: "r"(saddr), "l"(g));
}
#define CP_COMMIT() asm volatile("cp.async.commit_group;" ::: "memory")
#define CP_WAIT(N)  asm volatile("cp.async.wait_group %0;" :: "n"(N) : "memory")

// ---------------- Phase 0: pre-round feat & W to tf32 bits ----------------
__global__ __launch_bounds__(256) void preround_kernel(
    const float* __restrict__ feat, const float* __restrict__ W)
{
    int i = blockIdx.x * blockDim.x + threadIdx.x;
    if (i < (NPAD * IN_DIM) / 4) {
        float4 v = (i < (N_NODES * IN_DIM) / 4) ? ((const float4*)feat)[i]
                                                : make_float4(0.f, 0.f, 0.f, 0.f);
        uint4 o;
        o.x = rndf(v.x); o.y = rndf(v.y); o.z = rndf(v.z); o.w = rndf(v.w);
        ((uint4*)g_featr)[i] = o;
    }
    if (i < (N_ETYPE * IN_DIM * COM_DIM) / 4) {
        float4 v = ((const float4*)W)[i];
        uint4 o;
        o.x = rndf(v.x); o.y = rndf(v.y); o.z = rndf(v.z); o.w = rndf(v.w);
        ((uint4*)g_wr)[i] = o;
    }
}

// ---------------- Phase 1: mess = mask*(feat@W_t)+com, fused el/er ----------------
// 128Mx128N block tile, 8 warps (32Mx64N each), 2 CTAs/SM.
__global__ __launch_bounds__(256, 2)
void mma_kernel(const float* __restrict__ com, const float* __restrict__ mask,
                const float* __restrict__ attn_l, const float* __restrict__ attn_r)
{
    __shared__ float sAttn[8 * CPITCH];   // pre-scaled by log2(e)
    __shared__ float sMask[TILE_M];
    extern __shared__ float sh[];

    const int tid = threadIdx.x;
    const int wid = tid >> 5, lane = tid & 31;
    const int g = lane >> 2, tig = lane & 3;
    const int t = blockIdx.y;
    const int n0 = blockIdx.x * TILE_M;

    uint32_t shu;
    asm("{ .reg .u64 x; cvta.to.shared.u64 x, %1; cvt.u32.u64 %0, x; }" : "=r"(shu) : "l"(sh));

    for (int i = tid; i < 1024; i += 256) {
        int h = i >> 7, c = i & 127;
        float a = (h < 4) ? attn_l[(t * 4 + h) * 128 + c]
                          : attn_r[(t * 4 + (h - 4)) * 128 + c];
        sAttn[h * CPITCH + c] = a * LOG2E;
    }
    if (tid < TILE_M) {
        int gr = n0 + tid;
        sMask[tid] = (gr < N_NODES) ? mask[gr * N_ETYPE + t] : 0.f;
    }

    const uint32_t* Wt = g_wr + (size_t)t * IN_DIM * COM_DIM;

    auto load_chunk = [&](int c) {
        uint32_t abuf = shu + (uint32_t)((c & 1) ? A1OFF : A0OFF) * 4u;
        uint32_t bbuf = shu + (uint32_t)((c & 1) ? B1OFF : B0OFF) * 4u;
        #pragma unroll
        for (int jj = 0; jj < 4; ++jj) {                 // A: 128 x 32 words
            int j = tid + jj * 256;
            int row = j >> 3, seg = j & 7;
            cp16(abuf + (uint32_t)(row * APITCH + seg * 4) * 4u,
                 g_featr + (size_t)(n0 + row) * 128 + c * 32 + seg * 4);
        }
        #pragma unroll
        for (int jj = 0; jj < 4; ++jj) {                 // B: 32 x 128 words
            int j = tid + jj * 256;
            int kr = j >> 5, seg = j & 31;
            cp16(bbuf + (uint32_t)(kr * BPITCH + seg * 4) * 4u,
                 Wt + (size_t)(c * 32 + kr) * 128 + seg * 4);
        }
        CP_COMMIT();
    };

    const int mrow = (wid & 3) * 32;
    const int ncol = (wid >> 2) * 64;
    float acc[2][8][4];
    #pragma unroll
    for (int mb = 0; mb < 2; ++mb)
        #pragma unroll
        for (int nb = 0; nb < 8; ++nb)
            #pragma unroll
            for (int q = 0; q < 4; ++q) acc[mb][nb][q] = 0.f;

    load_chunk(0);
    for (int c = 0; c < 4; ++c) {
        if (c < 3) { load_chunk(c + 1); CP_WAIT(1); } else { CP_WAIT(0); }
        __syncthreads();

        const uint32_t* uA = (const uint32_t*)(sh + ((c & 1) ? A1OFF : A0OFF));
        const uint32_t* uB = (const uint32_t*)(sh + ((c & 1) ? B1OFF : B0OFF));
        #pragma unroll
        for (int ko = 0; ko < 32; ko += 8) {
            uint32_t a[2][4];
            #pragma unroll
            for (int mb = 0; mb < 2; ++mb) {
                int r = mrow + mb * 16;
                a[mb][0] = uA[(r + g) * APITCH + ko + tig];
                a[mb][1] = uA[(r + g + 8) * APITCH + ko + tig];
                a[mb][2] = uA[(r + g) * APITCH + ko + tig + 4];
                a[mb][3] = uA[(r + g + 8) * APITCH + ko + tig + 4];
            }
            #pragma unroll
            for (int nb = 0; nb < 8; ++nb) {
                int n = ncol + nb * 8 + g;
                uint32_t b0 = uB[(ko + tig) * BPITCH + n];
                uint32_t b1 = uB[(ko + tig + 4) * BPITCH + n];
                mma_tf32(acc[0][nb], a[0][0], a[0][1], a[0][2], a[0][3], b0, b1);
                mma_tf32(acc[1][nb], a[1][0], a[1][1], a[1][2], a[1][3], b0, b1);
            }
        }
        __syncthreads();
    }

    // ---- stage raw C into sC ----
    float* sC = sh;
    #pragma unroll
    for (int mb = 0; mb < 2; ++mb) {
        #pragma unroll
        for (int nb = 0; nb < 8; ++nb) {
            int r = mrow + mb * 16 + g;
            int cc = ncol + nb * 8 + 2 * tig;
            sC[r * CPITCH + cc]            = acc[mb][nb][0];
            sC[r * CPITCH + cc + 1]        = acc[mb][nb][1];
            sC[(r + 8) * CPITCH + cc]      = acc[mb][nb][2];
            sC[(r + 8) * CPITCH + cc + 1]  = acc[mb][nb][3];
        }
    }
    __syncthreads();

    // ---- mess pass: m = mk*C + com; fp16 -> gmem, fp32 -> sC ----
    for (int rr = 0; rr < 16; ++rr) {
        int r = wid * 16 + rr;
        int n = n0 + r;
        if (n >= N_NODES) break;
        float mk = sMask[r];
        float4 cv = *(const float4*)&sC[r * CPITCH + lane * 4];
        float4 cm = ((const float4*)com)[(size_t)n * 32 + lane];
        float4 m;
        m.x = fmaf(mk, cv.x, cm.x);
        m.y = fmaf(mk, cv.y, cm.y);
        m.z = fmaf(mk, cv.z, cm.z);
        m.w = fmaf(mk, cv.w, cm.w);
        __half2 h0 = __floats2half2_rn(m.x, m.y);
        __half2 h1 = __floats2half2_rn(m.z, m.w);
        uint2 pk;
        pk.x = *(uint32_t*)&h0;
        pk.y = *(uint32_t*)&h1;
        ((uint2*)(g_messh + ((size_t)t * N_NODES + n) * COM_DIM))[lane] = pk;
        *(float4*)&sC[r * CPITCH + lane * 4] = m;
    }
    __syncthreads();

    // ---- el/er dots (log2-scaled): lane = (row_sub, head) ----
    {
        const int r_sub = lane >> 3, v = lane & 7;
        #pragma unroll
        for (int it = 0; it < 4; ++it) {
            int r = wid * 16 + it * 4 + r_sub;
            int n = n0 + r;
            const float4* mrow4 = (const float4*)&sC[r * CPITCH];
            const float4* arow4 = (const float4*)&sAttn[v * CPITCH];
            float dot = 0.f;
            #pragma unroll
            for (int k4 = 0; k4 < 32; ++k4) {
                float4 mv = mrow4[k4];
                float4 av = arow4[k4];
                dot = fmaf(mv.x, av.x, dot);
                dot = fmaf(mv.y, av.y, dot);
                dot = fmaf(mv.z, av.z, dot);
                dot = fmaf(mv.w, av.w, dot);
            }
            if (n < N_NODES) {
                if (v < 4) g_el[(size_t)n * ELSTRIDE + v * N_ETYPE + t] = dot;
                else       g_er[(size_t)n * ELSTRIDE + (v - 4) * N_ETYPE + t] = dot;
            }
        }
    }
}

// ---------------- CSR build ----------------
__global__ void zero_kernel() {
    int i = blockIdx.x * blockDim.x + threadIdx.x;
    if (i < N_NODES) g_deg[i] = 0;
}
__global__ void hist_kernel(const int* __restrict__ dst) {
    int m = blockIdx.x * blockDim.x + threadIdx.x;
    if (m < N_EDGES) atomicAdd(&g_deg[dst[m]], 1);
}
__global__ __launch_bounds__(1024) void scanA_kernel() {
    __shared__ int wsum[32];
    const int tid = threadIdx.x, lane = tid & 31, wid = tid >> 5;
    int idx = blockIdx.x * 1024 + tid;
    int v = (idx < N_NODES) ? g_deg[idx] : 0;
    int x = v;
    #pragma unroll
    for (int off = 1; off < 32; off <<= 1) {
        int y = __shfl_up_sync(0xffffffffu, x, off);
        if (lane >= off) x += y;
    }
    if (lane == 31) wsum[wid] = x;
    __syncthreads();
    if (wid == 0) {
        int s = wsum[lane];
        #pragma unroll
        for (int off = 1; off < 32; off <<= 1) {
            int y = __shfl_up_sync(0xffffffffu, s, off);
            if (lane >= off) s += y;
        }
        wsum[lane] = s;
        if (lane == 31) g_bsum[blockIdx.x] = s;
    }
    __syncthreads();
    int excl = (x - v) + (wid > 0 ? wsum[wid - 1] : 0);
    if (idx < N_NODES) g_rowptr[idx] = excl;
}
__global__ void scanB_kernel() {
    int lane = threadIdx.x;
    int v = (lane < SCAN_BLK) ? g_bsum[lane] : 0;
    int x = v;
    #pragma unroll
    for (int off = 1; off < 32; off <<= 1) {
        int y = __shfl_up_sync(0xffffffffu, x, off);
        if (lane >= off) x += y;
    }
    __shared__ int tot32;
    if (lane == 31) tot32 = x;
    __syncwarp();
    g_boff[lane] = x - v;
    if (lane == 0) {
        int run = tot32;
        for (int b = 32; b < SCAN_BLK; ++b) {
            g_boff[b] = run;
            run += g_bsum[b];
        }
        g_rowptr[N_NODES] = N_EDGES;
    }
}
__global__ void scanC_kernel() {
    int i = blockIdx.x * blockDim.x + threadIdx.x;
    if (i < N_NODES) {
        int r = g_rowptr[i] + g_boff[i >> 10];
        g_rowptr[i] = r;
        g_deg[i] = r;
    }
}
// scatter packed (src | etype<<16) directly into CSR slots
__global__ void scatter_kernel(const int* __restrict__ dst, const int* __restrict__ src,
                               const int* __restrict__ etype) {
    int m = blockIdx.x * blockDim.x + threadIdx.x;
    if (m < N_EDGES) {
        int pos = atomicAdd(&g_deg[dst[m]], 1);
        g_epack[pos] = src[m] | (etype[m] << 16);
    }
}

// ---------------- Phase 3: softmax + aggregate + ELU (warp per dst) ----------------
__global__ __launch_bounds__(256) void agg_kernel(float* __restrict__ out)
{
    __shared__ float sEl[8 * 32 * ELP];   // per-warp staging: 32 edges x ELP
    int warp = (blockIdx.x * blockDim.x + threadIdx.x) >> 5;
    if (warp >= N_NODES) return;
    const int lane = threadIdx.x & 31;
    const int w = (threadIdx.x >> 5);
    const int d = warp;
    const int beg = g_rowptr[d], end = g_rowptr[d + 1];

    float* sElW = sEl + w * 32 * ELP;
    uint32_t sElU;
    asm("{ .reg .u64 x; cvta.to.shared.u64 x, %1; cvt.u32.u64 %0, x; }" : "=r"(sElU) : "l"(sElW));

    float er_l = g_er[(size_t)d * ELSTRIDE + lane];   // log2 domain

    // ---- pass 1 ----
    float den = 0.f;
    float4 enreg[2];
    enreg[0] = make_float4(0.f, 0.f, 0.f, 0.f);
    enreg[1] = make_float4(0.f, 0.f, 0.f, 0.f);
    int ci = 0;
    for (int base = beg; base < end; base += 32, ++ci) {
        int cnt = min(32, end - base);
        int s = 0, tt = 0;
        if (lane < cnt) {
            int pk = g_epack[base + lane];     // single coalesced load
            s = pk & 0xFFFF;
            tt = pk >> 16;
        }
        // stage el rows: edge p's 20 channels -> sElW[p*ELP + ch]  (lane = channel)
        for (int p = 0; p < cnt; ++p) {
            int sp = __shfl_sync(0xffffffffu, s, p);
            if (lane < NCH)
                cp4(sElU + (uint32_t)(p * ELP + lane) * 4u,
                    g_el + (size_t)sp * ELSTRIDE + lane);
        }
        CP_COMMIT();
        CP_WAIT(0);
        __syncwarp();

        // dense exp2: lane = edge, loop channels
        float4 en = make_float4(0.f, 0.f, 0.f, 0.f);
        #pragma unroll
        for (int ch = 0; ch < NCH; ++ch) {
            float erb = __shfl_sync(0xffffffffu, er_l, ch);
            float v = sElW[lane * ELP + ch] + erb;
            v = v >= 0.f ? v : NEG_SLOPE * v;
            float e = 0.f;
            if (lane < cnt) e = ex2(v);
            if (ch == tt)            en.x = e;
            else if (ch == tt + 5)   en.y = e;
            else if (ch == tt + 10)  en.z = e;
            else if (ch == tt + 15)  en.w = e;
            float sum = e;
            #pragma unroll
            for (int off = 16; off; off >>= 1)
                sum += __shfl_xor_sync(0xffffffffu, sum, off);
            if (lane == ch) den += sum;
        }
        if (ci < 2) enreg[ci] = en;
        else if (lane < cnt) ((float4*)g_enum)[base + lane] = en;
        __syncwarp();
    }
    float inv_den = (lane < NCH && den > 0.f) ? 1.f / den : 0.f;

    // ---- pass 2 ----
    float4 acc = make_float4(0.f, 0.f, 0.f, 0.f);
    ci = 0;
    for (int base = beg; base < end; base += 32, ++ci) {
        int cnt = min(32, end - base);
        int ri = 0, tt = 0;
        float4 en = make_float4(0.f, 0.f, 0.f, 0.f);
        if (lane < cnt) {
            int pk = g_epack[base + lane];
            int s = pk & 0xFFFF;
            tt = pk >> 16;
            ri = tt * N_NODES + s;
            en = (ci < 2) ? enreg[ci] : ((const float4*)g_enum)[base + lane];
        }
        float id0 = __shfl_sync(0xffffffffu, inv_den, tt);
        float id1 = __shfl_sync(0xffffffffu, inv_den, tt + 5);
        float id2 = __shfl_sync(0xffffffffu, inv_den, tt + 10);
        float id3 = __shfl_sync(0xffffffffu, inv_den, tt + 15);
        float cp = en.x * id0 + en.y * id1 + en.z * id2 + en.w * id3;

        for (int p0 = 0; p0 < cnt; p0 += 4) {
            int k = min(4, cnt - p0);
            uint2 pk4[4];
            float cc[4];
            #pragma unroll
            for (int j = 0; j < 4; ++j) {
                if (j < k) {
                    int rj = __shfl_sync(0xffffffffu, ri, p0 + j);
                    cc[j] = __shfl_sync(0xffffffffu, cp, p0 + j);
                    pk4[j] = ((const uint2*)(g_messh + (size_t)rj * COM_DIM))[lane];
                } else {
                    cc[j] = 0.f;
                    pk4[j] = make_uint2(0u, 0u);
                }
            }
            #pragma unroll
            for (int j = 0; j < 4; ++j) {
                __half2 h0 = *(__half2*)&pk4[j].x;
                __half2 h1 = *(__half2*)&pk4[j].y;
                float2 f0 = __half22float2(h0);
                float2 f1 = __half22float2(h1);
                acc.x = fmaf(cc[j], f0.x, acc.x);
                acc.y = fmaf(cc[j], f0.y, acc.y);
                acc.z = fmaf(cc[j], f1.x, acc.z);
                acc.w = fmaf(cc[j], f1.y, acc.w);
            }
        }
    }
    float4 o;
    o.x = acc.x > 0.f ? acc.x : expm1f(acc.x);
    o.y = acc.y > 0.f ? acc.y : expm1f(acc.y);
    o.z = acc.z > 0.f ? acc.z : expm1f(acc.z);
    o.w = acc.w > 0.f ? acc.w : expm1f(acc.w);
    ((float4*)out)[(size_t)d * 32 + lane] = o;
}

// ---------------- launch ----------------
extern "C" void kernel_launch(void* const* d_in, const int* in_sizes, int n_in,
                              void* d_out, int out_size)
{
    const float* feat   = (const float*)d_in[0];
    const float* com    = (const float*)d_in[1];
    const float* mask   = (const float*)d_in[2];
    const float* W      = (const float*)d_in[3];
    const float* attn_l = (const float*)d_in[4];
    const float* attn_r = (const float*)d_in[5];
    const int*   src    = (const int*)d_in[6];
    const int*   dst    = (const int*)d_in[7];
    const int*   etype  = (const int*)d_in[8];
    float* out = (float*)d_out;

    const int smem = SH_WORDS * (int)sizeof(float);   // 71680 B
    cudaFuncSetAttribute(mma_kernel, cudaFuncAttributeMaxDynamicSharedMemorySize, smem);

    const int pr_grid = ((NPAD * IN_DIM) / 4 + 255) / 256;

    // mma_kernel kept at launch index 3 (ncu capture slot)
    zero_kernel<<<(N_NODES + 255) / 256, 256>>>();
    hist_kernel<<<(N_EDGES + 255) / 256, 256>>>(dst);
    preround_kernel<<<pr_grid, 256>>>(feat, W);
    mma_kernel<<<dim3(NTILES, N_ETYPE), 256, smem>>>(com, mask, attn_l, attn_r);
    scanA_kernel<<<SCAN_BLK, 1024>>>();
    scanB_kernel<<<1, 32>>>();
    scanC_kernel<<<(N_NODES + 255) / 256, 256>>>();
    scatter_kernel<<<(N_EDGES + 255) / 256, 256>>>(dst, src, etype);
    agg_kernel<<<(N_NODES * 32 + 255) / 256, 256>>>(out);
}